// round 3
// baseline (speedup 1.0000x reference)
#include <cuda_runtime.h>
#include <cuda_bf16.h>
#include <cstdint>

// Problem dims
constexpr int BS  = 32;
constexpr int SEQ = 2048;
constexpr int IN  = 512;
constexpr int H   = 256;
constexpr int M0  = BS * SEQ;          // 65536 rows
constexpr int XXSZ = BS * SEQ * 2 * H; // 33554432 floats (xx output)

// ---------------- scratch (device globals; no allocation allowed) -----------
__device__ float g_H1[M0 * H];       // input projection  (64 MB)
__device__ float g_G0[M0 * H];       // layer-0 gates     (64 MB)
__device__ float g_Y0[2 * M0 * H];   // layer-0 outputs, ltr then rtl (128 MB)
__device__ float g_G1[2 * M0 * H];   // layer-1 gates     (128 MB)

// ---------------- small helpers ---------------------------------------------
__device__ __forceinline__ uint32_t f2tf(float x) {
    uint32_t u;
    asm("cvt.rna.tf32.f32 %0, %1;" : "=r"(u) : "f"(x));
    return u;
}

__device__ __forceinline__ void cp16(float* s, const float* g) {
    uint32_t sa = (uint32_t)__cvta_generic_to_shared(s);
    asm volatile("cp.async.cg.shared.global [%0], [%1], 16;\n" :: "r"(sa), "l"(g));
}
__device__ __forceinline__ void cp_commit() {
    asm volatile("cp.async.commit_group;\n" ::: "memory");
}
__device__ __forceinline__ void cp_wait1() {
    asm volatile("cp.async.wait_group 1;\n" ::: "memory");
}
__device__ __forceinline__ void cp_wait0() {
    asm volatile("cp.async.wait_group 0;\n" ::: "memory");
}

__device__ __forceinline__ void mma_tf32(float c[4], const uint32_t a[4], const uint32_t b[2]) {
    asm volatile(
        "mma.sync.aligned.m16n8k8.row.col.f32.tf32.tf32.f32 "
        "{%0,%1,%2,%3}, {%4,%5,%6,%7}, {%8,%9}, {%0,%1,%2,%3};\n"
        : "+f"(c[0]), "+f"(c[1]), "+f"(c[2]), "+f"(c[3])
        : "r"(a[0]), "r"(a[1]), "r"(a[2]), "r"(a[3]), "r"(b[0]), "r"(b[1]));
}

// accurate-enough tanh: ex2.approx + rcp.approx (rel err ~1e-6)
__device__ __forceinline__ float tanh_e(float p) {
    float z = p * 2.8853900817779268f;  // 2*log2(e)
    float e;   asm("ex2.approx.f32 %0, %1;" : "=f"(e) : "f"(z));
    float d = e + 1.0f;
    float inv; asm("rcp.approx.f32 %0, %1;" : "=f"(inv) : "f"(d));
    return fmaf(-2.0f, inv, 1.0f);      // 1 - 2/(e^{2p}+1)
}

// ---------------- GEMM: C[M,256] = act(A[M,K] @ W[256,K]^T + bias) ----------
// tiles: 128x128x32, 256 threads (8 warps, 2x4), tf32 warp MMA, cp.async DB.
constexpr int TBM = 128, TBN = 128, TBK = 32, LDT = 36;
constexpr int GEMM_SMEM = 2 * 2 * TBM * LDT * (int)sizeof(float);  // 73728 B

template <int ACT>
__launch_bounds__(256, 1)
__global__ void gemm_kernel(const float* __restrict__ A, const float* __restrict__ W,
                            const float* __restrict__ bias, float* __restrict__ C,
                            int M, int K) {
    extern __shared__ float smem[];
    float* As = smem;                 // [2][128][36]
    float* Bs = smem + 2 * TBM * LDT; // [2][128][36]

    const int tid  = threadIdx.x;
    const int warp = tid >> 5, lane = tid & 31;
    const int wm = (warp & 1) * 64;
    const int wn = (warp >> 1) * 32;
    const int bm = blockIdx.x * TBM;
    const int bn = blockIdx.y * TBN;

    float acc[4][4][4];
#pragma unroll
    for (int i = 0; i < 4; i++)
#pragma unroll
        for (int j = 0; j < 4; j++)
#pragma unroll
            for (int k = 0; k < 4; k++) acc[i][j][k] = 0.f;

    auto load_tile = [&](int kt, int buf) {
        const float* Ag = A + bm * K + kt * TBK;
        const float* Wg = W + bn * K + kt * TBK;
        float* Asb = As + buf * TBM * LDT;
        float* Bsb = Bs + buf * TBM * LDT;
#pragma unroll
        for (int i = 0; i < 4; i++) {
            int idx = i * 256 + tid;
            int row = idx >> 3, c4 = (idx & 7) * 4;
            cp16(Asb + row * LDT + c4, Ag + row * K + c4);
            cp16(Bsb + row * LDT + c4, Wg + row * K + c4);
        }
    };

    const int KT = K / TBK;
    load_tile(0, 0);
    cp_commit();

    for (int kt = 0; kt < KT; kt++) {
        const int cur = kt & 1;
        if (kt + 1 < KT) {
            load_tile(kt + 1, cur ^ 1);
            cp_commit();
            cp_wait1();
        } else {
            cp_wait0();
        }
        __syncthreads();

        const float* __restrict__ Asb = As + cur * TBM * LDT;
        const float* __restrict__ Bsb = Bs + cur * TBM * LDT;
        const int r0 = wm + (lane >> 2);
        const int kc = lane & 3;
#pragma unroll
        for (int kk = 0; kk < 4; kk++) {
            uint32_t a[4][4], b[4][2];
#pragma unroll
            for (int mi = 0; mi < 4; mi++) {
                int r = r0 + mi * 16;
                a[mi][0] = f2tf(Asb[r * LDT + kk * 8 + kc]);
                a[mi][1] = f2tf(Asb[(r + 8) * LDT + kk * 8 + kc]);
                a[mi][2] = f2tf(Asb[r * LDT + kk * 8 + kc + 4]);
                a[mi][3] = f2tf(Asb[(r + 8) * LDT + kk * 8 + kc + 4]);
            }
#pragma unroll
            for (int ni = 0; ni < 4; ni++) {
                int n = wn + ni * 8 + (lane >> 2);
                b[ni][0] = f2tf(Bsb[n * LDT + kk * 8 + kc]);
                b[ni][1] = f2tf(Bsb[n * LDT + kk * 8 + kc + 4]);
            }
#pragma unroll
            for (int mi = 0; mi < 4; mi++)
#pragma unroll
                for (int ni = 0; ni < 4; ni++) mma_tf32(acc[mi][ni], a[mi], b[ni]);
        }
        __syncthreads();
    }

    // epilogue: bias (+ sigmoid)
#pragma unroll
    for (int mi = 0; mi < 4; mi++) {
        int row = bm + wm + mi * 16 + (lane >> 2);
#pragma unroll
        for (int ni = 0; ni < 4; ni++) {
            int col = bn + wn + ni * 8 + (lane & 3) * 2;
            float b0 = bias[col], b1 = bias[col + 1];
            float v0 = acc[mi][ni][0] + b0;
            float v1 = acc[mi][ni][1] + b1;
            float v2 = acc[mi][ni][2] + b0;
            float v3 = acc[mi][ni][3] + b1;
            if (ACT) {
                v0 = 1.f / (1.f + __expf(-v0));
                v1 = 1.f / (1.f + __expf(-v1));
                v2 = 1.f / (1.f + __expf(-v2));
                v3 = 1.f / (1.f + __expf(-v3));
            }
            *(float2*)(C + row * 256 + col)       = make_float2(v0, v1);
            *(float2*)(C + (row + 8) * 256 + col) = make_float2(v2, v3);
        }
    }
}

// ---------------- fused bidirectional scan ----------------------------------
// One thread owns chain (b,f) for BOTH directions (2 interleaved dep chains).
// h_t = tanh(x_t * (g_t*(h_{t-1}-x_t) + x_t)) ; 8-deep register prefetch.
constexpr int PF = 8;

__global__ void scan_pair_kernel(
    const float* __restrict__ Xl, const float* __restrict__ Gl, float* __restrict__ Yl,
    const float* __restrict__ Xr, const float* __restrict__ Gr, float* __restrict__ Yr,
    int ldY, float* __restrict__ hfl, float* __restrict__ hfr) {
    const int gid = blockIdx.x * blockDim.x + threadIdx.x;  // 0..8191
    const int b = gid >> 8, f = gid & 255;

    int xl = b * SEQ * H + f;                    // t = 0, ascending
    int xr = b * SEQ * H + (SEQ - 1) * H + f;    // t = SEQ-1, descending
    int yl = b * SEQ * ldY + f;
    int yr = b * SEQ * ldY + (SEQ - 1) * ldY + f;

    float hl = 0.f, hr = 0.f;
    float xbl[PF], gbl[PF], xbr[PF], gbr[PF];
#pragma unroll
    for (int i = 0; i < PF; i++) {
        xbl[i] = Xl[xl + i * H];  gbl[i] = Gl[xl + i * H];
        xbr[i] = Xr[xr - i * H];  gbr[i] = Gr[xr - i * H];
    }
    int pl = xl + PF * H, pr = xr - PF * H;

#pragma unroll 1
    for (int s0 = 0; s0 < SEQ; s0 += PF) {
#pragma unroll
        for (int j = 0; j < PF; j++) {
            float x  = xbl[j], g  = gbl[j];
            float x2 = xbr[j], g2 = gbr[j];
            if (s0 + PF + j < SEQ) {
                xbl[j] = Xl[pl + j * H];  gbl[j] = Gl[pl + j * H];
                xbr[j] = Xr[pr - j * H];  gbr[j] = Gr[pr - j * H];
            }
            float r  = fmaf(g,  hl - x,  x);
            hl = tanh_e(x * r);
            Yl[yl] = hl;  yl += ldY;
            float r2 = fmaf(g2, hr - x2, x2);
            hr = tanh_e(x2 * r2);
            Yr[yr] = hr;  yr -= ldY;
        }
        pl += PF * H;  pr -= PF * H;
    }
    hfl[gid] = hl;   // ltr final hidden (t = SEQ-1)
    hfr[gid] = hr;   // rtl final hidden (t = 0, post-unflip)
}

// ---------------- launch ----------------------------------------------------
extern "C" void kernel_launch(void* const* d_in, const int* in_sizes, int n_in,
                              void* d_out, int out_size) {
    const float* x    = (const float*)d_in[0];
    const float* W_fc = (const float*)d_in[1];
    const float* b_fc = (const float*)d_in[2];
    // d_in[3]=W1, d_in[4]=b1 are mathematically dead (blending1 == identity)
    const float* W2   = (const float*)d_in[5];
    const float* b2   = (const float*)d_in[6];
    float* out = (float*)d_out;

    static float *pH1 = nullptr, *pG0 = nullptr, *pY0 = nullptr, *pG1 = nullptr;
    static bool inited = false;
    if (!inited) {
        cudaGetSymbolAddress((void**)&pH1, g_H1);
        cudaGetSymbolAddress((void**)&pG0, g_G0);
        cudaGetSymbolAddress((void**)&pY0, g_Y0);
        cudaGetSymbolAddress((void**)&pG1, g_G1);
        cudaFuncSetAttribute(gemm_kernel<0>, cudaFuncAttributeMaxDynamicSharedMemorySize, GEMM_SMEM);
        cudaFuncSetAttribute(gemm_kernel<1>, cudaFuncAttributeMaxDynamicSharedMemorySize, GEMM_SMEM);
        inited = true;
    }

    float* ho = out + XXSZ;  // h_out section: 4 slots of [32,256]

    // 1) input projection: H1 = x @ W_fc^T + b_fc           [65536,512]x[256,512]
    gemm_kernel<0><<<dim3(M0 / TBM, 2), 256, GEMM_SMEM>>>(x, W_fc, b_fc, pH1, M0, IN);
    // 2) layer-0 gates (shared by both directions): G0 = sigmoid(H1 @ W2_0^T + b2_0)
    gemm_kernel<1><<<dim3(M0 / TBM, 2), 256, GEMM_SMEM>>>(pH1, W2, b2, pG0, M0, H);
    // 3) layer-0 bidirectional scan -> Y0 (ltr half, rtl half in original t order)
    scan_pair_kernel<<<128, 64>>>(pH1, pG0, pY0,
                                  pH1, pG0, pY0 + M0 * H,
                                  H, ho, ho + BS * H);
    // 4) layer-1 gates over both halves at once: G1 = sigmoid(Y0 @ W2_1^T + b2_1)
    gemm_kernel<1><<<dim3(2 * M0 / TBM, 2), 256, GEMM_SMEM>>>(pY0, W2 + H * H, b2 + H, pG1, 2 * M0, H);
    // 5) layer-1 scan writing straight into d_out's [b,t,2H] layout + h_out
    scan_pair_kernel<<<128, 64>>>(pY0, pG1, out,
                                  pY0 + M0 * H, pG1 + M0 * H, out + H,
                                  2 * H, ho + 2 * BS * H, ho + 3 * BS * H);
}

// round 6
// speedup vs baseline: 1.2514x; 1.2514x over previous
#include <cuda_runtime.h>
#include <cuda_bf16.h>
#include <cstdint>

// Problem dims
constexpr int BS  = 32;
constexpr int SEQ = 2048;
constexpr int IN  = 512;
constexpr int H   = 256;
constexpr int M0  = BS * SEQ;          // 65536 rows
constexpr int XXSZ = BS * SEQ * 2 * H; // 33554432 floats (xx output)

constexpr int WFC_N = H * IN;          // 131072
constexpr int W2_N  = 2 * H * H;       // 131072

// ---------------- scratch (device globals; no allocation allowed) -----------
__device__ float g_H1[M0 * H];       // input projection  (64 MB)
__device__ float g_G0[M0 * H];       // layer-0 gates     (64 MB)
__device__ float g_Y0[2 * M0 * H];   // layer-0 outputs, ltr then rtl (128 MB)
__device__ float g_G1[2 * M0 * H];   // layer-1 gates     (128 MB)
__device__ float g_Wr[WFC_N + W2_N]; // tf32-prerounded weights (1 MB)

// ---------------- small helpers ---------------------------------------------
__device__ __forceinline__ uint32_t f2tf(float x) {
    uint32_t u;
    asm("cvt.rna.tf32.f32 %0, %1;" : "=r"(u) : "f"(x));
    return u;
}

__device__ __forceinline__ void cp16(float* s, const float* g) {
    uint32_t sa = (uint32_t)__cvta_generic_to_shared(s);
    asm volatile("cp.async.cg.shared.global [%0], [%1], 16;\n" :: "r"(sa), "l"(g));
}
__device__ __forceinline__ void cp_commit() {
    asm volatile("cp.async.commit_group;\n" ::: "memory");
}
__device__ __forceinline__ void cp_wait1() {
    asm volatile("cp.async.wait_group 1;\n" ::: "memory");
}
__device__ __forceinline__ void cp_wait0() {
    asm volatile("cp.async.wait_group 0;\n" ::: "memory");
}

__device__ __forceinline__ void mma_tf32(float c[4], const uint32_t a[4], const uint32_t b[2]) {
    asm volatile(
        "mma.sync.aligned.m16n8k8.row.col.f32.tf32.tf32.f32 "
        "{%0,%1,%2,%3}, {%4,%5,%6,%7}, {%8,%9}, {%0,%1,%2,%3};\n"
        : "+f"(c[0]), "+f"(c[1]), "+f"(c[2]), "+f"(c[3])
        : "r"(a[0]), "r"(a[1]), "r"(a[2]), "r"(a[3]), "r"(b[0]), "r"(b[1]));
}

// accurate-enough tanh pieces: ex2.approx + rcp.approx (rel err ~1e-6)
__device__ __forceinline__ float ex2f(float z) {
    float e; asm("ex2.approx.f32 %0, %1;" : "=f"(e) : "f"(z)); return e;
}
__device__ __forceinline__ float rcpf(float d) {
    float r; asm("rcp.approx.f32 %0, %1;" : "=f"(r) : "f"(d)); return r;
}

// ---------------- weight pre-round to tf32 (bitwise == cvt.rna per use) -----
__global__ void round_w_kernel(const float* __restrict__ Wfc,
                               const float* __restrict__ W2,
                               float* __restrict__ out) {
    int i = blockIdx.x * blockDim.x + threadIdx.x;
    if (i < WFC_N) {
        out[i] = __uint_as_float(f2tf(Wfc[i]));
    } else if (i < WFC_N + W2_N) {
        out[i] = __uint_as_float(f2tf(W2[i - WFC_N]));
    }
}

// ---------------- GEMM: C[M,256] = act(A[M,K] @ W[256,K]^T + bias) ----------
// tiles: 128x128x32, 256 threads = 8 warps laid out 4(m) x 2(n),
// warp tile 32x64. W is pre-rounded tf32 -> B frags need no cvt.
constexpr int TBM = 128, TBN = 128, TBK = 32, LDT = 36;
constexpr int GEMM_SMEM = 2 * 2 * TBM * LDT * (int)sizeof(float);  // 73728 B

template <int ACT>
__launch_bounds__(256, 2)
__global__ void gemm_kernel(const float* __restrict__ A, const float* __restrict__ W,
                            const float* __restrict__ bias, float* __restrict__ C,
                            int M, int K) {
    extern __shared__ float smem[];
    float* As = smem;                 // [2][128][36]
    float* Bs = smem + 2 * TBM * LDT; // [2][128][36]

    const int tid  = threadIdx.x;
    const int warp = tid >> 5, lane = tid & 31;
    const int wm = (warp >> 1) * 32;   // 4 distinct m-slabs (A redundancy 2x)
    const int wn = (warp & 1) * 64;    // 2 distinct n-slabs
    const int bm = blockIdx.x * TBM;
    const int bn = blockIdx.y * TBN;

    float acc[2][8][4];
#pragma unroll
    for (int i = 0; i < 2; i++)
#pragma unroll
        for (int j = 0; j < 8; j++)
#pragma unroll
            for (int k = 0; k < 4; k++) acc[i][j][k] = 0.f;

    auto load_tile = [&](int kt, int buf) {
        const float* Ag = A + bm * K + kt * TBK;
        const float* Wg = W + bn * K + kt * TBK;
        float* Asb = As + buf * TBM * LDT;
        float* Bsb = Bs + buf * TBM * LDT;
#pragma unroll
        for (int i = 0; i < 4; i++) {
            int idx = i * 256 + tid;
            int row = idx >> 3, c4 = (idx & 7) * 4;
            cp16(Asb + row * LDT + c4, Ag + row * K + c4);
            cp16(Bsb + row * LDT + c4, Wg + row * K + c4);
        }
    };

    const int KT = K / TBK;
    load_tile(0, 0);
    cp_commit();

    for (int kt = 0; kt < KT; kt++) {
        const int cur = kt & 1;
        if (kt + 1 < KT) {
            load_tile(kt + 1, cur ^ 1);
            cp_commit();
            cp_wait1();
        } else {
            cp_wait0();
        }
        __syncthreads();

        const float* __restrict__ Asb = As + cur * TBM * LDT;
        const float* __restrict__ Bsb = Bs + cur * TBM * LDT;
        const int r0 = wm + (lane >> 2);
        const int kc = lane & 3;
#pragma unroll
        for (int kk = 0; kk < 4; kk++) {
            uint32_t a[2][4], b[8][2];
#pragma unroll
            for (int mi = 0; mi < 2; mi++) {
                int r = r0 + mi * 16;
                a[mi][0] = f2tf(Asb[r * LDT + kk * 8 + kc]);
                a[mi][1] = f2tf(Asb[(r + 8) * LDT + kk * 8 + kc]);
                a[mi][2] = f2tf(Asb[r * LDT + kk * 8 + kc + 4]);
                a[mi][3] = f2tf(Asb[(r + 8) * LDT + kk * 8 + kc + 4]);
            }
#pragma unroll
            for (int ni = 0; ni < 8; ni++) {
                int n = wn + ni * 8 + (lane >> 2);
                // weights pre-rounded to tf32: raw bits are already canonical
                b[ni][0] = __float_as_uint(Bsb[n * LDT + kk * 8 + kc]);
                b[ni][1] = __float_as_uint(Bsb[n * LDT + kk * 8 + kc + 4]);
            }
#pragma unroll
            for (int mi = 0; mi < 2; mi++)
#pragma unroll
                for (int ni = 0; ni < 8; ni++) mma_tf32(acc[mi][ni], a[mi], b[ni]);
        }
        __syncthreads();
    }

    // epilogue: bias (+ sigmoid)
#pragma unroll
    for (int mi = 0; mi < 2; mi++) {
        int row = bm + wm + mi * 16 + (lane >> 2);
#pragma unroll
        for (int ni = 0; ni < 8; ni++) {
            int col = bn + wn + ni * 8 + (lane & 3) * 2;
            float b0 = bias[col], b1 = bias[col + 1];
            float v0 = acc[mi][ni][0] + b0;
            float v1 = acc[mi][ni][1] + b1;
            float v2 = acc[mi][ni][2] + b0;
            float v3 = acc[mi][ni][3] + b1;
            if (ACT) {
                v0 = 1.f / (1.f + __expf(-v0));
                v1 = 1.f / (1.f + __expf(-v1));
                v2 = 1.f / (1.f + __expf(-v2));
                v3 = 1.f / (1.f + __expf(-v3));
            }
            *(float2*)(C + row * 256 + col)       = make_float2(v0, v1);
            *(float2*)(C + (row + 8) * 256 + col) = make_float2(v2, v3);
        }
    }
}

// ---------------- fused bidirectional scan ----------------------------------
// One thread owns chain (b,f) for BOTH directions (2 interleaved dep chains).
// h_t = tanh(x_t*(g_t*h_{t-1} + x_t*(1-g_t))) ; 16-deep register prefetch so
// the 16*~48-cycle compute window exceeds DRAM latency; final block peeled.
constexpr int PF = 16;
constexpr float C2LOG2E = 2.8853900817779268f;  // 2*log2(e)

__global__ void scan_pair_kernel(
    const float* __restrict__ Xl, const float* __restrict__ Gl, float* __restrict__ Yl,
    const float* __restrict__ Xr, const float* __restrict__ Gr, float* __restrict__ Yr,
    int ldY, float* __restrict__ hfl, float* __restrict__ hfr) {
    const int gid = blockIdx.x * blockDim.x + threadIdx.x;  // 0..8191
    const int b = gid >> 8, f = gid & 255;

    int xl = b * SEQ * H + f;                    // t = 0, ascending
    int xr = b * SEQ * H + (SEQ - 1) * H + f;    // t = SEQ-1, descending
    int yl = b * SEQ * ldY + f;
    int yr = b * SEQ * ldY + (SEQ - 1) * ldY + f;

    float hl = 0.f, hr = 0.f;
    float xbl[PF], gbl[PF], xbr[PF], gbr[PF];
#pragma unroll
    for (int i = 0; i < PF; i++) {
        xbl[i] = Xl[xl + i * H];  gbl[i] = Gl[xl + i * H];
        xbr[i] = Xr[xr - i * H];  gbr[i] = Gr[xr - i * H];
    }
    int pl = xl + PF * H, pr = xr - PF * H;

    constexpr int NB = SEQ / PF;
#pragma unroll 1
    for (int blk = 0; blk < NB - 1; blk++) {
#pragma unroll
        for (int j = 0; j < PF; j++) {
            float x  = xbl[j], g  = gbl[j];
            float x2 = xbr[j], g2 = gbr[j];
            // refill (unconditional; last block peeled)
            xbl[j] = Xl[pl + j * H];  gbl[j] = Gl[pl + j * H];
            xbr[j] = Xr[pr - j * H];  gbr[j] = Gr[pr - j * H];
            // off-critical-path precompute
            float q  = fmaf(-g,  x,  x);    // x*(1-g)
            float xk = x  * C2LOG2E;
            float q2 = fmaf(-g2, x2, x2);
            float xk2 = x2 * C2LOG2E;
            // chain: fma, mul, ex2, add, rcp, fma  (~48 cyc)
            float r  = fmaf(g,  hl, q);
            float e  = ex2f(xk * r);
            hl = fmaf(-2.f, rcpf(e + 1.f), 1.f);
            Yl[yl] = hl;  yl += ldY;
            float r2 = fmaf(g2, hr, q2);
            float e2 = ex2f(xk2 * r2);
            hr = fmaf(-2.f, rcpf(e2 + 1.f), 1.f);
            Yr[yr] = hr;  yr -= ldY;
        }
        pl += PF * H;  pr -= PF * H;
    }
    // final block: consume only
#pragma unroll
    for (int j = 0; j < PF; j++) {
        float x  = xbl[j], g  = gbl[j];
        float x2 = xbr[j], g2 = gbr[j];
        float q  = fmaf(-g,  x,  x);
        float xk = x  * C2LOG2E;
        float q2 = fmaf(-g2, x2, x2);
        float xk2 = x2 * C2LOG2E;
        float r  = fmaf(g,  hl, q);
        float e  = ex2f(xk * r);
        hl = fmaf(-2.f, rcpf(e + 1.f), 1.f);
        Yl[yl] = hl;  yl += ldY;
        float r2 = fmaf(g2, hr, q2);
        float e2 = ex2f(xk2 * r2);
        hr = fmaf(-2.f, rcpf(e2 + 1.f), 1.f);
        Yr[yr] = hr;  yr -= ldY;
    }
    hfl[gid] = hl;   // ltr final hidden (t = SEQ-1)
    hfr[gid] = hr;   // rtl final hidden (t = 0, post-unflip)
}

// ---------------- launch ----------------------------------------------------
extern "C" void kernel_launch(void* const* d_in, const int* in_sizes, int n_in,
                              void* d_out, int out_size) {
    const float* x    = (const float*)d_in[0];
    const float* W_fc = (const float*)d_in[1];
    const float* b_fc = (const float*)d_in[2];
    // d_in[3]=W1, d_in[4]=b1 are mathematically dead (blending1 == identity)
    const float* W2   = (const float*)d_in[5];
    const float* b2   = (const float*)d_in[6];
    float* out = (float*)d_out;

    static float *pH1 = nullptr, *pG0 = nullptr, *pY0 = nullptr, *pG1 = nullptr, *pWr = nullptr;
    static bool inited = false;
    if (!inited) {
        cudaGetSymbolAddress((void**)&pH1, g_H1);
        cudaGetSymbolAddress((void**)&pG0, g_G0);
        cudaGetSymbolAddress((void**)&pY0, g_Y0);
        cudaGetSymbolAddress((void**)&pG1, g_G1);
        cudaGetSymbolAddress((void**)&pWr, g_Wr);
        cudaFuncSetAttribute(gemm_kernel<0>, cudaFuncAttributeMaxDynamicSharedMemorySize, GEMM_SMEM);
        cudaFuncSetAttribute(gemm_kernel<1>, cudaFuncAttributeMaxDynamicSharedMemorySize, GEMM_SMEM);
        inited = true;
    }

    float* ho = out + XXSZ;  // h_out section: 4 slots of [32,256]
    const float* Wfc_r = pWr;
    const float* W2_r  = pWr + WFC_N;

    // 0) pre-round weights to tf32 (bitwise identical to per-use cvt.rna)
    round_w_kernel<<<(WFC_N + W2_N + 255) / 256, 256>>>(W_fc, W2, pWr);
    // 1) input projection: H1 = x @ W_fc^T + b_fc           [65536,512]x[256,512]
    gemm_kernel<0><<<dim3(M0 / TBM, 2), 256, GEMM_SMEM>>>(x, Wfc_r, b_fc, pH1, M0, IN);
    // 2) layer-0 gates (shared by both directions): G0 = sigmoid(H1 @ W2_0^T + b2_0)
    gemm_kernel<1><<<dim3(M0 / TBM, 2), 256, GEMM_SMEM>>>(pH1, W2_r, b2, pG0, M0, H);
    // 3) layer-0 bidirectional scan -> Y0 (ltr half, rtl half in original t order)
    scan_pair_kernel<<<128, 64>>>(pH1, pG0, pY0,
                                  pH1, pG0, pY0 + M0 * H,
                                  H, ho, ho + BS * H);
    // 4) layer-1 gates over both halves at once: G1 = sigmoid(Y0 @ W2_1^T + b2_1)
    gemm_kernel<1><<<dim3(2 * M0 / TBM, 2), 256, GEMM_SMEM>>>(pY0, W2_r + H * H, b2 + H, pG1, 2 * M0, H);
    // 5) layer-1 scan writing straight into d_out's [b,t,2H] layout + h_out
    scan_pair_kernel<<<128, 64>>>(pY0, pG1, out,
                                  pY0 + M0 * H, pG1 + M0 * H, out + H,
                                  2 * H, ho + 2 * BS * H, ho + 3 * BS * H);
}